// round 10
// baseline (speedup 1.0000x reference)
#include <cuda_runtime.h>
#include <cuda_fp16.h>
#include <math.h>
#include <stdint.h>

constexpr int B_    = 2;
constexpr int NQ    = 2048;
constexpr int NKV   = 2048;
constexpr int D     = 1024;
constexpr int INNER = 1024;
constexpr int HEADS = 16;
constexpr int DIMH  = 64;

constexpr int ROWS = B_ * NQ; // 4096
constexpr float SCALE_LOG2E = 0.125f * 1.4426950408889634f;

// Scratch (allocation-free rule: __device__ globals)
__device__ __half g_Q[ROWS * INNER];
__device__ __half g_K[ROWS * INNER];
__device__ __half g_V[ROWS * INNER];
__device__ __half g_A[ROWS * INNER];
__device__ __half g_PA[ROWS * D];
__device__ __half g_PX[ROWS * D];
__device__ __half g_WQ[D * INNER];   // transposed weights [N][K]
__device__ __half g_WK[D * INNER];
__device__ __half g_WV[D * INNER];
__device__ __half g_WO[INNER * D];

// ---------------------------------------------------------------------------
// helpers
// ---------------------------------------------------------------------------
__device__ __forceinline__ void cp_async16(void* dst, const void* src) {
    uint32_t s = (uint32_t)__cvta_generic_to_shared(dst);
    asm volatile("cp.async.cg.shared.global [%0], [%1], 16;\n" :: "r"(s), "l"(src));
}
__device__ __forceinline__ void cp_commit() { asm volatile("cp.async.commit_group;\n"); }

__device__ __forceinline__ float ex2(float x) {
    float r; asm("ex2.approx.ftz.f32 %0, %1;" : "=f"(r) : "f"(x)); return r;
}
__device__ __forceinline__ uint32_t pack2(float lo, float hi) {
    uint32_t r;
    asm("cvt.rn.f16x2.f32 %0, %1, %2;" : "=r"(r) : "f"(hi), "f"(lo));
    return r;
}

__device__ __forceinline__ void mma_f16(float* c, const uint32_t* a, uint32_t b0, uint32_t b1) {
    asm volatile(
        "mma.sync.aligned.m16n8k16.row.col.f32.f16.f16.f32 "
        "{%0,%1,%2,%3}, {%4,%5,%6,%7}, {%8,%9}, {%0,%1,%2,%3};\n"
        : "+f"(c[0]), "+f"(c[1]), "+f"(c[2]), "+f"(c[3])
        : "r"(a[0]), "r"(a[1]), "r"(a[2]), "r"(a[3]), "r"(b0), "r"(b1));
}

__device__ __forceinline__ void ldmx4(uint32_t& r0, uint32_t& r1, uint32_t& r2, uint32_t& r3,
                                      const void* p) {
    uint32_t a = (uint32_t)__cvta_generic_to_shared(p);
    asm volatile("ldmatrix.sync.aligned.m8n8.x4.shared.b16 {%0,%1,%2,%3}, [%4];"
                 : "=r"(r0), "=r"(r1), "=r"(r2), "=r"(r3) : "r"(a));
}
__device__ __forceinline__ void ldmx4_trans(uint32_t& r0, uint32_t& r1, uint32_t& r2, uint32_t& r3,
                                            const void* p) {
    uint32_t a = (uint32_t)__cvta_generic_to_shared(p);
    asm volatile("ldmatrix.sync.aligned.m8n8.x4.trans.shared.b16 {%0,%1,%2,%3}, [%4];"
                 : "=r"(r0), "=r"(r1), "=r"(r2), "=r"(r3) : "r"(a));
}
__device__ __forceinline__ void ldmx2_trans(uint32_t& r0, uint32_t& r1, const void* p) {
    uint32_t a = (uint32_t)__cvta_generic_to_shared(p);
    asm volatile("ldmatrix.sync.aligned.m8n8.x2.trans.shared.b16 {%0,%1}, [%2];"
                 : "=r"(r0), "=r"(r1) : "r"(a));
}

// ---------------------------------------------------------------------------
// prep kernels
// ---------------------------------------------------------------------------
// 4 float4 per thread (MLP=4), two tensors via blockIdx.y
__global__ void cvth4(__half* __restrict__ d0, const float4* __restrict__ s0,
                      __half* __restrict__ d1, const float4* __restrict__ s1,
                      int n4, int stride) {
    const int base = blockIdx.x * blockDim.x + threadIdx.x;
    const float4* s = blockIdx.y ? s1 : s0;
    __half* d = blockIdx.y ? d1 : d0;
    float4 v[4];
#pragma unroll
    for (int k = 0; k < 4; k++) {
        const int i = base + k * stride;
        v[k] = s[i];
    }
#pragma unroll
    for (int k = 0; k < 4; k++) {
        const int i = base + k * stride;
        uint2 o;
        o.x = pack2(v[k].x, v[k].y);
        o.y = pack2(v[k].z, v[k].w);
        *reinterpret_cast<uint2*>(d + 4 * (size_t)i) = o;
    }
}

__global__ void transpose_cvt4(__half* __restrict__ d0, const float* __restrict__ s0,
                               __half* __restrict__ d1, const float* __restrict__ s1,
                               __half* __restrict__ d2, const float* __restrict__ s2,
                               __half* __restrict__ d3, const float* __restrict__ s3) {
    __shared__ float t[32][33];
    const int z = blockIdx.z;
    const float* src = (z == 0) ? s0 : (z == 1) ? s1 : (z == 2) ? s2 : s3;
    __half* dst = (z == 0) ? d0 : (z == 1) ? d1 : (z == 2) ? d2 : d3;
    const int n0 = blockIdx.x * 32;
    const int k0 = blockIdx.y * 32;
    const int tx = threadIdx.x, ty = threadIdx.y;
#pragma unroll
    for (int i = 0; i < 4; i++)
        t[ty + i * 8][tx] = src[(size_t)(k0 + ty + i * 8) * 1024 + n0 + tx];
    __syncthreads();
#pragma unroll
    for (int i = 0; i < 4; i++)
        dst[(size_t)(n0 + ty + i * 8) * 1024 + k0 + tx] = __float2half_rn(t[tx][ty + i * 8]);
}

// ---------------------------------------------------------------------------
// fp16 GEMM (unchanged): 4-stage cp.async, ldmatrix frag loads.
// ---------------------------------------------------------------------------
constexpr int HG_LD = 40;
constexpr int HG_TILE = 128 * HG_LD;
constexpr int HG_STAGES = 4;
constexpr int HG_SMEM = HG_STAGES * 2 * HG_TILE * 2; // 81920 B

template <bool QKV, bool HALF_OUT, bool BIAS>
__global__ __launch_bounds__(256, 2)
void hgemm(const __half* __restrict__ A0, const __half* __restrict__ W0, void* __restrict__ C0,
           const __half* __restrict__ A1, const __half* __restrict__ W1, void* __restrict__ C1,
           const __half* __restrict__ A2, const __half* __restrict__ W2, void* __restrict__ C2,
           const float* __restrict__ bias, int M, int N, int K, float oscale0) {
    extern __shared__ __half sh[];

    const __half* A = A0; const __half* WT = W0; void* Cv = C0;
    float oscale = oscale0;
    if (QKV) {
        const int z = blockIdx.z;
        if (z == 1) { A = A1; WT = W1; Cv = C1; oscale = 1.0f; }
        else if (z == 2) { A = A2; WT = W2; Cv = C2; oscale = 1.0f; }
    }

    const int tid  = threadIdx.x;
    const int wid  = tid >> 5;
    const int lane = tid & 31;
    const int g    = lane >> 2;
    const int tig  = lane & 3;
    const int wm = wid >> 1;
    const int wn = wid & 1;
    const int bm0 = blockIdx.y * 128;
    const int bn0 = blockIdx.x * 128;
    const int lmr = lane & 15;
    const int lmc = (lane >> 4) * 8;

    float acc[2][8][4];
#pragma unroll
    for (int mi = 0; mi < 2; mi++)
#pragma unroll
        for (int nb = 0; nb < 8; nb++)
#pragma unroll
            for (int e = 0; e < 4; e++) acc[mi][nb][e] = 0.0f;

    auto load_tiles = [&](int buf, int k0) {
#pragma unroll
        for (int i = 0; i < 2; i++) {
            const int idx = tid + i * 256;
            const int r = idx >> 2, c = idx & 3;
            cp_async16(&sh[buf * 2 * HG_TILE + r * HG_LD + c * 8],
                       &A[(size_t)(bm0 + r) * K + k0 + c * 8]);
        }
#pragma unroll
        for (int i = 0; i < 2; i++) {
            const int idx = tid + i * 256;
            const int r = idx >> 2, c = idx & 3;
            cp_async16(&sh[buf * 2 * HG_TILE + HG_TILE + r * HG_LD + c * 8],
                       &WT[(size_t)(bn0 + r) * K + k0 + c * 8]);
        }
    };

    const int KT = K / 32;
    load_tiles(0, 0);  cp_commit();
    load_tiles(1, 32); cp_commit();
    load_tiles(2, 64); cp_commit();

    for (int t = 0; t < KT; t++) {
        const int buf = t & 3;
        asm volatile("cp.async.wait_group 2;\n");
        __syncthreads();
        if (t + 3 < KT) { load_tiles((t + 3) & 3, (t + 3) * 32); cp_commit(); }

        const __half* Ab = sh + buf * 2 * HG_TILE;
        const __half* Bb = Ab + HG_TILE;
#pragma unroll
        for (int ks = 0; ks < 2; ks++) {
            uint32_t a[2][4];
            uint32_t b[4][4];
#pragma unroll
            for (int mi = 0; mi < 2; mi++)
                ldmx4(a[mi][0], a[mi][1], a[mi][2], a[mi][3],
                      Ab + (wm * 32 + mi * 16 + lmr) * HG_LD + ks * 16 + lmc);
#pragma unroll
            for (int nbp = 0; nbp < 4; nbp++)
                ldmx4(b[nbp][0], b[nbp][1], b[nbp][2], b[nbp][3],
                      Bb + (wn * 64 + nbp * 16 + lmr) * HG_LD + ks * 16 + lmc);
#pragma unroll
            for (int nbp = 0; nbp < 4; nbp++)
#pragma unroll
                for (int mi = 0; mi < 2; mi++) {
                    mma_f16(acc[mi][2 * nbp],     a[mi], b[nbp][0], b[nbp][2]);
                    mma_f16(acc[mi][2 * nbp + 1], a[mi], b[nbp][1], b[nbp][3]);
                }
        }
    }

#pragma unroll
    for (int mi = 0; mi < 2; mi++) {
        const int row0 = bm0 + wm * 32 + mi * 16 + g;
#pragma unroll
        for (int nb = 0; nb < 8; nb++) {
            const int col = bn0 + wn * 64 + nb * 8 + 2 * tig;
            float c0 = acc[mi][nb][0] * oscale, c1 = acc[mi][nb][1] * oscale;
            float c2 = acc[mi][nb][2] * oscale, c3 = acc[mi][nb][3] * oscale;
            if (BIAS) {
                const float b0 = bias[col], b1 = bias[col + 1];
                c0 += b0; c1 += b1; c2 += b0; c3 += b1;
            }
            if (HALF_OUT) {
                __half* C = (__half*)Cv;
                *reinterpret_cast<uint32_t*>(&C[(size_t)row0 * N + col])       = pack2(c0, c1);
                *reinterpret_cast<uint32_t*>(&C[(size_t)(row0 + 8) * N + col]) = pack2(c2, c3);
            } else {
                float* C = (float*)Cv;
                *reinterpret_cast<float2*>(&C[(size_t)row0 * N + col])       = make_float2(c0, c1);
                *reinterpret_cast<float2*>(&C[(size_t)(row0 + 8) * N + col]) = make_float2(c2, c3);
            }
        }
    }
}

// ---------------------------------------------------------------------------
// fp16 flash attention v6: balance-friendly shape.
//  - 256 thr (8 warps x 16 q-rows), q-tile 128 per block, grid 512, 2 blk/SM
//    -> 16 warps/SM, wave efficiency ~86.5% (vs 58% in v5)
//  - unnormalized p = ex2(s); row sums via ones-column mma (V pad col64 = 1)
// ---------------------------------------------------------------------------
constexpr int ALD = 72;                       // halves per K/V row (144B stride)
constexpr int ATILE = 64 * ALD;               // halves per tile
constexpr int ATT_SMEM = 2 * 2 * ATILE * 2;   // 36864 B
constexpr int AGRID6 = (NQ / 128) * HEADS * B_;  // 512

__global__ __launch_bounds__(256, 2)
void attn6(const __half* __restrict__ Q, const __half* __restrict__ K,
           const __half* __restrict__ V, __half* __restrict__ O) {
    extern __shared__ __half sh[];

    const int tid  = threadIdx.x;
    const int w    = tid >> 5;        // 0..7
    const int lane = tid & 31;
    const int g    = lane >> 2;
    const int tig  = lane & 3;
    const int lmr = lane & 15;
    const int lmc = (lane >> 4) * 8;

    const int qt = blockIdx.x & 15;
    const int hb = blockIdx.x >> 4;
    const int h  = hb & 15;
    const int b  = hb >> 4;
    const int q0 = qt * 128;

    // ones-pad init: V tiles' cols 64-71 = [1,0,...] in both buffers
    if (tid < 128) {
        const int buf = tid >> 6, r = tid & 63;
        uint4 ones = make_uint4(0x00003C00u, 0u, 0u, 0u);
        *reinterpret_cast<uint4*>(sh + (buf * 2 + 1) * ATILE + r * ALD + 64) = ones;
    }

    const __half* Kg = K + (size_t)(b * NKV) * INNER + h * DIMH;
    const __half* Vg = V + (size_t)(b * NKV) * INNER + h * DIMH;

    // Q A-frags: 16 rows per warp (r0, r0+8). Pre-scaled by scale*log2e.
    uint32_t qa[4][4];
    const int r0 = q0 + w * 16 + g;
    {
        const __half* Q0 = Q + (size_t)(b * NQ + r0) * INNER + h * DIMH;
        const __half* Q1 = Q0 + 8 * (size_t)INNER;
#pragma unroll
        for (int kk = 0; kk < 4; kk++) {
            qa[kk][0] = *reinterpret_cast<const uint32_t*>(Q0 + kk * 16 + 2 * tig);
            qa[kk][1] = *reinterpret_cast<const uint32_t*>(Q1 + kk * 16 + 2 * tig);
            qa[kk][2] = *reinterpret_cast<const uint32_t*>(Q0 + kk * 16 + 2 * tig + 8);
            qa[kk][3] = *reinterpret_cast<const uint32_t*>(Q1 + kk * 16 + 2 * tig + 8);
        }
    }

    float oa[8][4];
    float sum[4] = {0.f, 0.f, 0.f, 0.f};
#pragma unroll
    for (int nb = 0; nb < 8; nb++)
#pragma unroll
        for (int e = 0; e < 4; e++) oa[nb][e] = 0.0f;

    auto prefetch = [&](int buf, int j0) {
#pragma unroll
        for (int i = 0; i < 2; i++) {   // K: 512 chunks / 256 thr
            const int idx = tid + i * 256;
            const int r = idx >> 3, c = idx & 7;
            cp_async16(&sh[buf * 2 * ATILE + r * ALD + c * 8],
                       Kg + (size_t)(j0 + r) * INNER + c * 8);
        }
#pragma unroll
        for (int i = 0; i < 2; i++) {   // V
            const int idx = tid + i * 256;
            const int r = idx >> 3, c = idx & 7;
            cp_async16(&sh[buf * 2 * ATILE + ATILE + r * ALD + c * 8],
                       Vg + (size_t)(j0 + r) * INNER + c * 8);
        }
    };

    prefetch(0, 0);
    cp_commit();

    constexpr int NT = NKV / 64;
    for (int t = 0; t < NT; t++) {
        const int buf = t & 1;
        asm volatile("cp.async.wait_group 0;\n");
        __syncthreads();
        if (t + 1 < NT) { prefetch(buf ^ 1, (t + 1) * 64); cp_commit(); }

        const __half* Kb = sh + buf * 2 * ATILE;
        const __half* Vb = Kb + ATILE;

#pragma unroll
        for (int nbp = 0; nbp < 4; nbp++) {
            // S chunk: 16 rows x 16 cols
            float s0[4] = {0.f, 0.f, 0.f, 0.f};
            float s1[4] = {0.f, 0.f, 0.f, 0.f};
#pragma unroll
            for (int kk = 0; kk < 4; kk++) {
                uint32_t b0, b1, b2, b3;
                ldmx4(b0, b1, b2, b3, Kb + (nbp * 16 + lmr) * ALD + kk * 16 + lmc);
                mma_f16(s0, qa[kk], b0, b2);
                mma_f16(s1, qa[kk], b1, b3);
            }
            // p = ex2(s), unnormalized; pack to A-frags
            uint32_t pa[4];
            pa[0] = pack2(ex2(s0[0]), ex2(s0[1]));
            pa[1] = pack2(ex2(s0[2]), ex2(s0[3]));
            pa[2] = pack2(ex2(s1[0]), ex2(s1[1]));
            pa[3] = pack2(ex2(s1[2]), ex2(s1[3]));

            // O += P V
#pragma unroll
            for (int j = 0; j < 4; j++) {
                uint32_t b0, b1, b2, b3;
                ldmx4_trans(b0, b1, b2, b3, Vb + (nbp * 16 + lmr) * ALD + j * 16 + lmc);
                mma_f16(oa[2 * j],     pa, b0, b1);
                mma_f16(oa[2 * j + 1], pa, b2, b3);
            }
            // row sums via ones column
            {
                uint32_t c0, c1;
                ldmx2_trans(c0, c1, Vb + (nbp * 16 + lmr) * ALD + 64);
                mma_f16(sum, pa, c0, c1);
            }
        }
    }

    // extract row sums (col 64 lives in tig==0 lanes: sum[0]=row g, sum[2]=row g+8)
    const int src = lane & 28;
    const float inv0 = 1.0f / __shfl_sync(0xffffffffu, sum[0], src);
    const float inv1 = 1.0f / __shfl_sync(0xffffffffu, sum[2], src);

    __half* O0 = O + (size_t)(b * NQ + r0) * INNER + h * DIMH;
    __half* O1 = O0 + 8 * (size_t)INNER;
#pragma unroll
    for (int nb = 0; nb < 8; nb++) {
        *reinterpret_cast<uint32_t*>(O0 + nb * 8 + 2 * tig) =
            pack2(oa[nb][0] * inv0, oa[nb][1] * inv0);
        *reinterpret_cast<uint32_t*>(O1 + nb * 8 + 2 * tig) =
            pack2(oa[nb][2] * inv1, oa[nb][3] * inv1);
    }
}

// ---------------------------------------------------------------------------
extern "C" void kernel_launch(void* const* d_in, const int* in_sizes, int n_in,
                              void* d_out, int out_size) {
    const float* patch = (const float*)d_in[0];
    const float* pixel = (const float*)d_in[1];
    const float* Wq    = (const float*)d_in[2];
    const float* Wk    = (const float*)d_in[3];
    const float* Wv    = (const float*)d_in[4];
    const float* Wo    = (const float*)d_in[5];
    const float* bo    = (const float*)d_in[6];
    float* out = (float*)d_out;

    __half *pQ, *pK, *pV, *pA, *pPA, *pPX, *pWQ, *pWK, *pWV, *pWO;
    cudaGetSymbolAddress((void**)&pQ,  g_Q);
    cudaGetSymbolAddress((void**)&pK,  g_K);
    cudaGetSymbolAddress((void**)&pV,  g_V);
    cudaGetSymbolAddress((void**)&pA,  g_A);
    cudaGetSymbolAddress((void**)&pPA, g_PA);
    cudaGetSymbolAddress((void**)&pPX, g_PX);
    cudaGetSymbolAddress((void**)&pWQ, g_WQ);
    cudaGetSymbolAddress((void**)&pWK, g_WK);
    cudaGetSymbolAddress((void**)&pWV, g_WV);
    cudaGetSymbolAddress((void**)&pWO, g_WO);

    cudaFuncSetAttribute((const void*)hgemm<true, true, false>,
                         cudaFuncAttributeMaxDynamicSharedMemorySize, HG_SMEM);
    cudaFuncSetAttribute((const void*)hgemm<false, false, true>,
                         cudaFuncAttributeMaxDynamicSharedMemorySize, HG_SMEM);
    cudaFuncSetAttribute(attn6, cudaFuncAttributeMaxDynamicSharedMemorySize, ATT_SMEM);

    // 1) prep: activations -> fp16 (MLP=4); weight transposes (merged)
    const int actN4 = ROWS * D / 4;              // 1048576
    const int cvblocks = actN4 / (4 * 256);      // 1024
    cvth4<<<dim3(cvblocks, 2), 256>>>(pPA, (const float4*)patch,
                                      pPX, (const float4*)pixel,
                                      actN4, cvblocks * 256);
    transpose_cvt4<<<dim3(32, 32, 4), dim3(32, 8)>>>(pWQ, Wq, pWK, Wk, pWV, Wv, pWO, Wo);

    // 2) Q/K/V projections (one launch); Q scaled by scale*log2e
    dim3 ggrid(INNER / 128, ROWS / 128, 3);
    hgemm<true, true, false><<<ggrid, 256, HG_SMEM>>>(
        pPA, pWQ, pQ, pPX, pWK, pK, pPX, pWV, pV, nullptr, ROWS, INNER, D, SCALE_LOG2E);

    // 3) attention (q-tile 128, grid 512, 2 blocks/SM)
    attn6<<<AGRID6, 256, ATT_SMEM>>>(pQ, pK, pV, pA);

    // 4) output projection + bias (fp32 out)
    dim3 ogrid(D / 128, ROWS / 128, 1);
    hgemm<false, false, true><<<ogrid, 256, HG_SMEM>>>(
        pA, pWO, out, nullptr, nullptr, nullptr, nullptr, nullptr, nullptr,
        bo, ROWS, D, INNER, 1.0f);
}